// round 12
// baseline (speedup 1.0000x reference)
#include <cuda_runtime.h>
#include <cstdint>

// Problem shape (fixed dataset): preds (16,2048,78) f32, targets (16,32,78) f32,
// masks (16,32) bool (encoding sniffed), img_w=800. Output: concat(assigned_mask,
// matched) as FLOAT32, 2*B*P elements.

#define BB 16
#define PP 2048
#define GG 32
#define DD 78
#define NN 72
#define HN 36   // points per half-thread
#define QI 10   // top-k depth for iou (SIMOTA_Q)
#define QC 9    // candidate depth for cost (k <= 9 provable: each iou < 1)
#define GZ 4    // z-slices of the gt loop
#define GPB (GG / GZ)   // gts per block = 8

// Scratch (device globals; no allocation allowed)
__device__ float2 g_ci[BB * GG * PP];                // 8 MB: (.x=cost, .y=iou), [b][g][p]
__device__ unsigned long long g_akey[BB * PP];       // packed (fkey(cost)<<32)|g

// mask decode helper: sniff element width from word0.
//   byte bool all-true -> 0x01010101 ; int32 true -> 0x00000001 ; f32 1.0 -> 0x3F800000
__device__ __forceinline__ int mask_is_word(const unsigned char* m) {
    unsigned int w0 = *(const unsigned int*)m;
    return (w0 == 1u || w0 == 0x3F800000u) ? 1 : 0;
}
__device__ __forceinline__ bool mask_at(const unsigned char* m, int enc, int i) {
    return enc ? (((const unsigned int*)m)[i] != 0u) : (m[i] != 0);
}

__device__ __forceinline__ unsigned int fkey(float f) {
    unsigned int u = __float_as_uint(f);
    return (u & 0x80000000u) ? ~u : (u | 0x80000000u);  // monotone total order
}

// ---------------------------------------------------------------------------
// Kernel 1: pairwise cost + iou. Two threads per prior (lane pair), 36 points
// each -> line[36] keeps regs ~60 -> ~50% occupancy (vs 22% with line[72]).
// Partial |line-gx| sums combined with shfl_xor(1); even lane does epilogue.
// ---------------------------------------------------------------------------
__global__ __launch_bounds__(256) void cost_kernel(
    const float* __restrict__ preds,
    const float* __restrict__ targets,
    const unsigned char* __restrict__ masks,
    const int* __restrict__ imgw_p)
{
    const int b = blockIdx.y;
    const int p0 = blockIdx.x * 128;
    const int half = threadIdx.x & 1;          // 0 or 1: which 36-point half
    const int p = p0 + (threadIdx.x >> 1);     // prior owned by this lane pair
    const int g0 = blockIdx.z * GPB;

    // robust scalar decode: int32/int64 little-endian, or float32 bits
    int iw = imgw_p ? *imgw_p : 800;
    if (iw <= 0 || iw > 100000) {
        float fw = imgw_p ? __int_as_float(iw) : 800.0f;
        iw = (fw >= 1.0f && fw <= 100000.0f) ? (int)fw : 800;
    }
    const float img_w = (float)iw;
    const float scale = img_w - 1.0f;

    __shared__ float4 s_gx4[GPB][NN / 4];  // masked gt points gxm = v*gx
    __shared__ float4 s_v4 [GPB][NN / 4];  // valid flags (generic path only)
    __shared__ float  s_t2[GPB], s_t3[GPB], s_t4[GPB];
    __shared__ float  s_nv30[GPB];
    __shared__ float  s_m[GPB];
    __shared__ int    s_av[GPB];           // all-valid flag per gt

    float* s_gx = (float*)s_gx4;
    float* s_v  = (float*)s_v4;

    for (int idx = threadIdx.x; idx < GPB * DD; idx += 256) {
        int g = idx / DD, d = idx - g * DD;
        float v = targets[((size_t)b * GG + g0 + g) * DD + d];
        if (d == 2)      s_t2[g] = v;
        else if (d == 3) s_t3[g] = v;
        else if (d == 4) s_t4[g] = v;
        if (d >= 6) {
            float x = v * scale;
            bool valid = (x >= 0.0f) && (x < img_w);
            s_gx[g * NN + (d - 6)] = valid ? x : 0.0f;   // masked gx
            s_v [g * NN + (d - 6)] = valid ? 1.0f : 0.0f;
        }
    }
    if (threadIdx.x < GPB) {
        int enc = mask_is_word(masks);
        s_m[threadIdx.x] = mask_at(masks, enc, b * GG + g0 + threadIdx.x) ? 1.0f : 0.0f;
    }
    __syncthreads();
    if (threadIdx.x < GPB) {
        float nv = 0.0f;
        for (int n = 0; n < NN; n++) nv += s_v[threadIdx.x * NN + n];
        s_nv30[threadIdx.x] = 30.0f * nv;
        s_av[threadIdx.x] = (nv == (float)NN) ? 1 : 0;
    }
    __syncthreads();

    // init assignment key once per (b,p)
    if (blockIdx.z == 0 && half == 0)
        g_akey[b * PP + p] = 0xFFFFFFFFFFFFFFFFull;

    const float* row = preds + ((size_t)b * PP + p) * DD;

    // this half's 36 line points (float2-aligned: 6 + 36*half both even)
    float line[HN];
    {
        const float2* rl = (const float2*)(row + 6 + HN * half);
#pragma unroll
        for (int i = 0; i < HN / 2; i++) {
            float2 t = rl[i];
            line[2 * i]     = t.x * scale;
            line[2 * i + 1] = t.y * scale;
        }
    }

    // epilogue inputs: even lane only
    float cls3 = 0.0f, pr2 = 0.0f, pr3 = 0.0f, pr4 = 0.0f;
    if (half == 0) {
        const float2* rh = (const float2*)row;
        float2 h01 = rh[0], h23 = rh[1];
        pr2 = h23.x; pr3 = h23.y; pr4 = row[4];
        float mx = fmaxf(h01.x, h01.y);
        float e0 = expf(h01.x - mx), e1 = expf(h01.y - mx);
        cls3 = -3.0f * logf(fmaxf(e1 / (e0 + e1), 1e-8f));
    }

    const int n4ofs = half * (HN / 4);   // 0 or 9

#pragma unroll
    for (int g = 0; g < GPB; g++) {
        float S0 = 0.0f, S1 = 0.0f, S2 = 0.0f, S3 = 0.0f;
        if (s_av[g]) {
#pragma unroll
            for (int n4 = 0; n4 < HN / 4; n4++) {
                float4 gx = s_gx4[g][n4ofs + n4];
                S0 += fabsf(line[4 * n4 + 0] - gx.x);
                S1 += fabsf(line[4 * n4 + 1] - gx.y);
                S2 += fabsf(line[4 * n4 + 2] - gx.z);
                S3 += fabsf(line[4 * n4 + 3] - gx.w);
            }
        } else {
            // generic: v*|line-gx| = |v*line - gxm|
#pragma unroll
            for (int n4 = 0; n4 < HN / 4; n4++) {
                float4 gx = s_gx4[g][n4ofs + n4];
                float4 v  = s_v4[g][n4ofs + n4];
                S0 += fabsf(fmaf(v.x, line[4 * n4 + 0], -gx.x));
                S1 += fabsf(fmaf(v.y, line[4 * n4 + 1], -gx.y));
                S2 += fabsf(fmaf(v.z, line[4 * n4 + 2], -gx.z));
                S3 += fabsf(fmaf(v.w, line[4 * n4 + 3], -gx.w));
            }
        }
        float S = (S0 + S1) + (S2 + S3);
        S += __shfl_xor_sync(0xFFFFFFFFu, S, 1);   // combine lane pair

        if (half == 0) {
            float nv30 = s_nv30[g];
            float iou = (nv30 - S) / (nv30 + S + 1e-9f);
            float m = s_m[g];
            iou = iou * m;
            float reg = fabsf(pr3 - s_t3[g]) + fabsf(pr2 - s_t2[g]) + fabsf(pr4 - s_t4[g]);
            float iouc = (m > 0.0f) ? -logf(fmaxf(iou, 1e-8f)) : 0.0f;
            float total = cls3 + 3.0f * reg + 3.0f * iouc + 1e5f * (1.0f - m);
            g_ci[((size_t)(b * GG + g0 + g)) * PP + p] = make_float2(total, iou);
        }
    }
}

// ---------------------------------------------------------------------------
// Kernel 2: per-(b,g) selection + assignment scatter.
//   k = clip((int)(sum of top-10 iou over priors), 1, P)   (k <= 9 since iou < 1)
//   candidates = k smallest costs under lexicographic (cost, index)
//   Assignment per prior = lexicographic min over (cost, g) -> atomicMin of
//   packed key (fkey(cost)<<32 | g).
// ---------------------------------------------------------------------------
__global__ __launch_bounds__(256) void select_kernel(const unsigned char* __restrict__ masks)
{
    const int bg = blockIdx.x;
    const float2* ci = g_ci + (size_t)bg * PP;
    const int tid = threadIdx.x;

    float ti[QI];                 // descending top-10 iou
    unsigned long long tc[QC];    // ascending bottom-9 (cost,idx) keys
#pragma unroll
    for (int j = 0; j < QI; j++) ti[j] = -3.4e38f;
#pragma unroll
    for (int j = 0; j < QC; j++) tc[j] = 0xFFFFFFFFFFFFFFFFull;

    for (int p = tid; p < PP; p += 256) {
        float2 v2 = __ldg(ci + p);
        float v = v2.y;
        if (v > ti[QI - 1]) {     // early skip
#pragma unroll
            for (int j = 0; j < QI; j++) {
                if (v > ti[j]) { float t = ti[j]; ti[j] = v; v = t; }
            }
        }
        unsigned long long key =
            ((unsigned long long)fkey(v2.x) << 32) | (unsigned int)p;
        if (key < tc[QC - 1]) {   // early skip
#pragma unroll
            for (int j = 0; j < QC; j++) {
                if (key < tc[j]) { unsigned long long t = tc[j]; tc[j] = key; key = t; }
            }
        }
    }

    __shared__ float s_i[256][QI];
    __shared__ unsigned long long s_c[256][QC];
#pragma unroll
    for (int j = 0; j < QI; j++) s_i[tid][j] = ti[j];
#pragma unroll
    for (int j = 0; j < QC; j++) s_c[tid][j] = tc[j];
    __syncthreads();

    for (int stride = 128; stride >= 1; stride >>= 1) {
        if (tid < stride) {
            float oi[QI]; unsigned long long oc[QC];
            int i = 0, j = 0;
#pragma unroll
            for (int t = 0; t < QI; t++) {
                float av = s_i[tid][i], bv = s_i[tid + stride][j];
                if (av >= bv) { oi[t] = av; i++; } else { oi[t] = bv; j++; }
            }
            i = 0; j = 0;
#pragma unroll
            for (int t = 0; t < QC; t++) {
                unsigned long long av = s_c[tid][i], bv = s_c[tid + stride][j];
                if (av <= bv) { oc[t] = av; i++; } else { oc[t] = bv; j++; }
            }
#pragma unroll
            for (int t = 0; t < QI; t++) s_i[tid][t] = oi[t];
#pragma unroll
            for (int t = 0; t < QC; t++) s_c[tid][t] = oc[t];
        }
        __syncthreads();
    }

    if (tid == 0) {
        float sum = 0.0f;
        for (int j = 0; j < QI; j++) sum += s_i[0][j];   // descending == top_k order
        int k = (int)sum;            // astype(int32): truncate toward zero
        if (k < 1)  k = 1;           // clip(., 1, P)
        if (k > QC) k = QC;          // provably <= 9
        int enc = mask_is_word(masks);
        if (!mask_at(masks, enc, bg)) k = 0;   // invalid gt selects nothing
        int b = bg / GG;
        unsigned int g = (unsigned int)(bg % GG);
        for (int j = 0; j < k; j++) {
            unsigned long long key = s_c[0][j];
            int p = (int)(key & 0xFFFFFFFFull);
            unsigned int ck = (unsigned int)(key >> 32);
            if (ck != 0xFFFFFFFFu) {
                unsigned long long akey = ((unsigned long long)ck << 32) | g;
                atomicMin(&g_akey[b * PP + p], akey);   // fire-and-forget RED
            }
        }
    }
}

// ---------------------------------------------------------------------------
// Kernel 3: fully-parallel output writer.
// ---------------------------------------------------------------------------
__global__ __launch_bounds__(256) void output_kernel(float* __restrict__ out)
{
    int i = blockIdx.x * 256 + threadIdx.x;        // i in [0, BB*PP)
    unsigned long long key = g_akey[i];
    bool matched = (key != 0xFFFFFFFFFFFFFFFFull);
    int g = (int)(key & 0xFFFFFFFFull);
    out[i] = matched ? 1.0f : 0.0f;                        // assigned_mask
    out[BB * PP + i] = matched ? (float)g : -1.0f;         // matched
}

// ---------------------------------------------------------------------------
extern "C" void kernel_launch(void* const* d_in, const int* in_sizes, int n_in,
                              void* d_out, int out_size)
{
    const float* preds   = (const float*)d_in[0];
    const float* targets = (const float*)d_in[1];
    const unsigned char* masks = (const unsigned char*)d_in[2];
    const int* imgw = (n_in > 3) ? (const int*)d_in[3] : nullptr;

    cost_kernel<<<dim3(PP / 128, BB, GZ), 256>>>(preds, targets, masks, imgw);
    select_kernel<<<BB * GG, 256>>>(masks);
    output_kernel<<<(BB * PP) / 256, 256>>>((float*)d_out);
}

// round 14
// speedup vs baseline: 1.4938x; 1.4938x over previous
#include <cuda_runtime.h>
#include <cstdint>

// Problem shape (fixed dataset): preds (16,2048,78) f32, targets (16,32,78) f32,
// masks (16,32) bool (encoding sniffed), img_w=800. Output: concat(assigned_mask,
// matched) as FLOAT32, 2*B*P elements.

#define BB 16
#define PP 2048
#define GG 32
#define DD 78
#define NN 72
#define QI 10   // top-k depth for iou (SIMOTA_Q)
#define QC 9    // candidate depth for cost (k <= 9 provable: each iou < 1)
#define GZ 4    // z-slices of the gt loop
#define GPB (GG / GZ)   // gts per block = 8
#define NCH 9            // chunks of 8 points
#define NU  (NN / 2)     // 36 ull (f32x2 containers) per gt row

typedef unsigned long long ull;

// Scratch (device globals; no allocation allowed)
__device__ float2 g_ci[BB * GG * PP];                // 8 MB: (.x=cost, .y=iou), [b][g][p]
__device__ ull    g_akey[BB * PP];                   // packed (fkey(cost)<<32)|g

// mask decode helper: sniff element width from word0.
__device__ __forceinline__ int mask_is_word(const unsigned char* m) {
    unsigned int w0 = *(const unsigned int*)m;
    return (w0 == 1u || w0 == 0x3F800000u) ? 1 : 0;
}
__device__ __forceinline__ bool mask_at(const unsigned char* m, int enc, int i) {
    return enc ? (((const unsigned int*)m)[i] != 0u) : (m[i] != 0);
}

__device__ __forceinline__ unsigned int fkey(float f) {
    unsigned int u = __float_as_uint(f);
    return (u & 0x80000000u) ? ~u : (u | 0x80000000u);  // monotone total order
}

// packed f32x2 helpers (sm_103a): one instruction per 2 fp32 lanes
__device__ __forceinline__ void acc_pair(ull& S, ull v2, ull l2, ull n2) {
    ull d;
    asm("fma.rn.f32x2 %0, %1, %2, %3;" : "=l"(d) : "l"(v2), "l"(l2), "l"(n2));
    d &= 0x7FFFFFFF7FFFFFFFull;                     // |.| both lanes (alu pipe)
    asm("add.rn.f32x2 %0, %1, %2;" : "=l"(S) : "l"(S), "l"(d));
}
__device__ __forceinline__ float hsum_pair(ull S) {
    unsigned int lo, hi;
    asm("mov.b64 {%0, %1}, %2;" : "=r"(lo), "=r"(hi) : "l"(S));
    return __uint_as_float(lo) + __uint_as_float(hi);
}

// ---------------------------------------------------------------------------
// Kernel 1: pairwise cost + iou; f32x2-packed inner loop, chunked accumulators
// (regs ~50 -> 8 CTAs/SM). S computed in RAW units, scaled once at the end:
//   S_px = scale * sum |v*line_raw - v*gx_raw|   (ngxm = -v*gx_raw in smem)
// ---------------------------------------------------------------------------
__global__ __launch_bounds__(128, 8) void cost_kernel(
    const float* __restrict__ preds,
    const float* __restrict__ targets,
    const unsigned char* __restrict__ masks,
    const int* __restrict__ imgw_p)
{
    const int b = blockIdx.y;
    const int p = blockIdx.x * 128 + threadIdx.x;
    const int g0 = blockIdx.z * GPB;

    // robust scalar decode: int32/int64 little-endian, or float32 bits
    int iw = imgw_p ? *imgw_p : 800;
    if (iw <= 0 || iw > 100000) {
        float fw = imgw_p ? __int_as_float(iw) : 800.0f;
        iw = (fw >= 1.0f && fw <= 100000.0f) ? (int)fw : 800;
    }
    const float img_w = (float)iw;
    const float scale = img_w - 1.0f;

    __shared__ ull   s_ngxm[GPB * NU];   // -v*gx_raw, packed pairs (16B-aligned)
    __shared__ ull   s_v   [GPB * NU];   // valid flags, packed pairs
    __shared__ float s_t2[GPB], s_t3[GPB], s_t4[GPB];
    __shared__ float s_nv30[GPB];
    __shared__ float s_m[GPB];

    float* f_ngxm = (float*)s_ngxm;
    float* f_v    = (float*)s_v;

    for (int idx = threadIdx.x; idx < GPB * DD; idx += 128) {
        int g = idx / DD, d = idx - g * DD;
        float t = targets[((size_t)b * GG + g0 + g) * DD + d];
        if (d == 2)      s_t2[g] = t;
        else if (d == 3) s_t3[g] = t;
        else if (d == 4) s_t4[g] = t;
        if (d >= 6) {
            float xp = t * scale;                       // pixel-space validity
            bool valid = (xp >= 0.0f) && (xp < img_w);
            f_ngxm[g * NN + (d - 6)] = valid ? -t : 0.0f;
            f_v   [g * NN + (d - 6)] = valid ? 1.0f : 0.0f;
        }
    }
    if (threadIdx.x < GPB) {
        int enc = mask_is_word(masks);
        s_m[threadIdx.x] = mask_at(masks, enc, b * GG + g0 + threadIdx.x) ? 1.0f : 0.0f;
    }
    __syncthreads();
    if (threadIdx.x < GPB) {
        float nv = 0.0f;
        for (int n = 0; n < NN; n++) nv += f_v[threadIdx.x * NN + n];
        s_nv30[threadIdx.x] = 30.0f * nv;
    }
    __syncthreads();

    // init assignment key once per (b,p)
    if (blockIdx.z == 0)
        g_akey[b * PP + p] = 0xFFFFFFFFFFFFFFFFull;

    const float* row = preds + ((size_t)b * PP + p) * DD;
    // epilogue head loads (8B-aligned: row start even)
    const float2* rh = (const float2*)row;
    float2 h01 = rh[0], h23 = rh[1];
    float pr2 = h23.x, pr3 = h23.y, pr4 = row[4];
    float mx = fmaxf(h01.x, h01.y);
    float e0 = expf(h01.x - mx), e1 = expf(h01.y - mx);
    float cls3 = -3.0f * logf(fmaxf(e1 / (e0 + e1), 1e-8f));

    // packed accumulators, one per gt
    ull S2[GPB];
#pragma unroll
    for (int g = 0; g < GPB; g++) S2[g] = 0ull;

    // line pointer in f32x2 units ((row+6) is 8B-aligned: offset 6 even, row even)
    const ull* rl = (const ull*)(row + 6);

#pragma unroll
    for (int c = 0; c < NCH; c++) {               // 9 chunks of 8 points (4 pairs)
        ull l0 = rl[4 * c + 0], l1 = rl[4 * c + 1];
        ull l2 = rl[4 * c + 2], l3 = rl[4 * c + 3];
#pragma unroll
        for (int g = 0; g < GPB; g++) {
            const ulonglong2* ng = (const ulonglong2*)(s_ngxm + g * NU + 4 * c);
            const ulonglong2* vv = (const ulonglong2*)(s_v    + g * NU + 4 * c);
            ulonglong2 n01 = ng[0], n23 = ng[1];   // 2x LDS.128
            ulonglong2 v01 = vv[0], v23 = vv[1];   // 2x LDS.128
            acc_pair(S2[g], v01.x, l0, n01.x);
            acc_pair(S2[g], v01.y, l1, n01.y);
            acc_pair(S2[g], v23.x, l2, n23.x);
            acc_pair(S2[g], v23.y, l3, n23.y);
        }
    }

#pragma unroll
    for (int g = 0; g < GPB; g++) {
        float S = scale * hsum_pair(S2[g]);        // pixels
        float nv30 = s_nv30[g];
        float iou = (nv30 - S) / (nv30 + S + 1e-9f);
        float m = s_m[g];
        iou = iou * m;
        float reg = fabsf(pr3 - s_t3[g]) + fabsf(pr2 - s_t2[g]) + fabsf(pr4 - s_t4[g]);
        float iouc = (m > 0.0f) ? -logf(fmaxf(iou, 1e-8f)) : 0.0f;
        float total = cls3 + 3.0f * reg + 3.0f * iouc + 1e5f * (1.0f - m);
        g_ci[((size_t)(b * GG + g0 + g)) * PP + p] = make_float2(total, iou);
    }
}

// ---------------------------------------------------------------------------
// Kernel 2: per-(b,g) selection + assignment scatter (unchanged).
// ---------------------------------------------------------------------------
__global__ __launch_bounds__(256) void select_kernel(const unsigned char* __restrict__ masks)
{
    const int bg = blockIdx.x;
    const float2* ci = g_ci + (size_t)bg * PP;
    const int tid = threadIdx.x;

    float ti[QI];
    ull tc[QC];
#pragma unroll
    for (int j = 0; j < QI; j++) ti[j] = -3.4e38f;
#pragma unroll
    for (int j = 0; j < QC; j++) tc[j] = 0xFFFFFFFFFFFFFFFFull;

    for (int p = tid; p < PP; p += 256) {
        float2 v2 = __ldg(ci + p);
        float v = v2.y;
        if (v > ti[QI - 1]) {
#pragma unroll
            for (int j = 0; j < QI; j++) {
                if (v > ti[j]) { float t = ti[j]; ti[j] = v; v = t; }
            }
        }
        ull key = ((ull)fkey(v2.x) << 32) | (unsigned int)p;
        if (key < tc[QC - 1]) {
#pragma unroll
            for (int j = 0; j < QC; j++) {
                if (key < tc[j]) { ull t = tc[j]; tc[j] = key; key = t; }
            }
        }
    }

    __shared__ float s_i[256][QI];
    __shared__ ull s_c[256][QC];
#pragma unroll
    for (int j = 0; j < QI; j++) s_i[tid][j] = ti[j];
#pragma unroll
    for (int j = 0; j < QC; j++) s_c[tid][j] = tc[j];
    __syncthreads();

    for (int stride = 128; stride >= 1; stride >>= 1) {
        if (tid < stride) {
            float oi[QI]; ull oc[QC];
            int i = 0, j = 0;
#pragma unroll
            for (int t = 0; t < QI; t++) {
                float av = s_i[tid][i], bv = s_i[tid + stride][j];
                if (av >= bv) { oi[t] = av; i++; } else { oi[t] = bv; j++; }
            }
            i = 0; j = 0;
#pragma unroll
            for (int t = 0; t < QC; t++) {
                ull av = s_c[tid][i], bv = s_c[tid + stride][j];
                if (av <= bv) { oc[t] = av; i++; } else { oc[t] = bv; j++; }
            }
#pragma unroll
            for (int t = 0; t < QI; t++) s_i[tid][t] = oi[t];
#pragma unroll
            for (int t = 0; t < QC; t++) s_c[tid][t] = oc[t];
        }
        __syncthreads();
    }

    if (tid == 0) {
        float sum = 0.0f;
        for (int j = 0; j < QI; j++) sum += s_i[0][j];   // descending == top_k order
        int k = (int)sum;            // astype(int32): truncate toward zero
        if (k < 1)  k = 1;
        if (k > QC) k = QC;          // provably <= 9
        int enc = mask_is_word(masks);
        if (!mask_at(masks, enc, bg)) k = 0;
        int b = bg / GG;
        unsigned int g = (unsigned int)(bg % GG);
        for (int j = 0; j < k; j++) {
            ull key = s_c[0][j];
            int p = (int)(key & 0xFFFFFFFFull);
            unsigned int ck = (unsigned int)(key >> 32);
            if (ck != 0xFFFFFFFFu) {
                ull akey = ((ull)ck << 32) | g;
                atomicMin(&g_akey[b * PP + p], akey);   // fire-and-forget RED
            }
        }
    }
}

// ---------------------------------------------------------------------------
// Kernel 3: fully-parallel output writer (unchanged).
// ---------------------------------------------------------------------------
__global__ __launch_bounds__(256) void output_kernel(float* __restrict__ out)
{
    int i = blockIdx.x * 256 + threadIdx.x;        // i in [0, BB*PP)
    ull key = g_akey[i];
    bool matched = (key != 0xFFFFFFFFFFFFFFFFull);
    int g = (int)(key & 0xFFFFFFFFull);
    out[i] = matched ? 1.0f : 0.0f;                        // assigned_mask
    out[BB * PP + i] = matched ? (float)g : -1.0f;         // matched
}

// ---------------------------------------------------------------------------
extern "C" void kernel_launch(void* const* d_in, const int* in_sizes, int n_in,
                              void* d_out, int out_size)
{
    const float* preds   = (const float*)d_in[0];
    const float* targets = (const float*)d_in[1];
    const unsigned char* masks = (const unsigned char*)d_in[2];
    const int* imgw = (n_in > 3) ? (const int*)d_in[3] : nullptr;

    cost_kernel<<<dim3(PP / 128, BB, GZ), 128>>>(preds, targets, masks, imgw);
    select_kernel<<<BB * GG, 256>>>(masks);
    output_kernel<<<(BB * PP) / 256, 256>>>((float*)d_out);
}